// round 14
// baseline (speedup 1.0000x reference)
#include <cuda_runtime.h>
#include <cuda_bf16.h>
#include <math_constants.h>
#include <cstdint>
#include <cmath>

#define Nn   16384
#define Cc   64
#define Kk   32
#define Hh   128
#define OUTD 64
#define Ss   4          // candidate stripes per query
#define Mm   (Ss * Kk)  // candidates per query after filter (128)

// ---------------- scratch (static device globals) ---------------------------
__device__ float  g_A [Nn * Hh];
__device__ float  g_MX[Nn * Hh];
__device__ float  g_MN[Nn * Hh];
__device__ float  g_H1[Nn * Hh];
__device__ int    g_IDX[Nn * Kk];
__device__ float  g_NRM[Nn];
__device__ int    g_CI[Nn * Mm];               // filtered candidate indices
__device__ __nv_bfloat162 g_Xb[Nn * (Hh / 2)]; // bf16-packed features (filter only)
__device__ double g_sum1[Hh], g_ss1[Hh], g_sum2[Hh], g_ss2[Hh];
__device__ float  g_mu1[Hh], g_r1[Hh], g_mu2[Hh], g_r2[Hh];

__global__ void zero_stats_kernel() {
    int t = threadIdx.x;
    g_sum1[t] = 0.0; g_ss1[t] = 0.0;
    g_sum2[t] = 0.0; g_ss2[t] = 0.0;
}

// ---------------- prep: exact sequential norms + bf16 conversion ------------
template <int C>
__global__ void prep_kernel(const float* __restrict__ X, float* __restrict__ nrm,
                            __nv_bfloat162* __restrict__ Xb) {
    int n = blockIdx.x * blockDim.x + threadIdx.x;
    if (n >= Nn) return;
    const float4* r = (const float4*)(X + (size_t)n * C);
    __nv_bfloat162* ob = Xb + (size_t)n * (C / 2);
    float s = 0.f;
    #pragma unroll
    for (int u = 0; u < C / 4; u++) {
        float4 v = r[u];
        s = __fadd_rn(s, __fmul_rn(v.x, v.x));
        s = __fadd_rn(s, __fmul_rn(v.y, v.y));
        s = __fadd_rn(s, __fmul_rn(v.z, v.z));
        s = __fadd_rn(s, __fmul_rn(v.w, v.w));
        ob[2 * u]     = __floats2bfloat162_rn(v.x, v.y);
        ob[2 * u + 1] = __floats2bfloat162_rn(v.z, v.w);
    }
    nrm[n] = s;
}

// ---------------- KNN stage 1: approximate per-stripe top-K (bf16x2) --------
// d_approx = |x_j|^2 - 2 * dot_bf16(x_i, x_j)  (ranking only — exact pass
// downstream re-ranks with bit-exact fp32 sequential chains).
template <int C, int TC>
__global__ __launch_bounds__(128, 1)
void filter_knn_kernel(const __nv_bfloat162* __restrict__ Xb, const float* __restrict__ nrm,
                       int* __restrict__ out_ci) {
    __shared__ __nv_bfloat162 sXb[TC * (C / 2)];
    __shared__ float sN[TC];

    const int qi     = blockIdx.x * 128 + threadIdx.x;
    const int stripe = blockIdx.y;
    const int cand0  = stripe * (Nn / Ss);
    const int cand1  = cand0 + (Nn / Ss);

    uint4 qraw[C / 8];
    {
        const uint4* xq = (const uint4*)(Xb + (size_t)qi * (C / 2));
        #pragma unroll
        for (int u = 0; u < C / 8; u++) qraw[u] = xq[u];
    }
    const __nv_bfloat162* q2 = (const __nv_bfloat162*)qraw;

    float bd[Kk]; int bi[Kk];
    #pragma unroll
    for (int i = 0; i < Kk; i++) { bd[i] = CUDART_INF_F; bi[i] = 0; }
    float worst = CUDART_INF_F;
    int   wpos  = 0;

    const __nv_bfloat162 z2 = __floats2bfloat162_rn(0.f, 0.f);

    for (int t0 = cand0; t0 < cand1; t0 += TC) {
        __syncthreads();
        const uint4* src = (const uint4*)(Xb + (size_t)t0 * (C / 2));
        for (int l = threadIdx.x; l < TC * C / 8; l += 128) ((uint4*)sXb)[l] = src[l];
        for (int l = threadIdx.x; l < TC; l += 128) sN[l] = nrm[t0 + l];
        __syncthreads();

        for (int j0 = 0; j0 < TC; j0 += 4) {
            __nv_bfloat162 a0 = z2, a1 = z2, a2 = z2, a3 = z2;
            const __nv_bfloat162* p0 = &sXb[(j0 + 0) * (C / 2)];
            const __nv_bfloat162* p1 = &sXb[(j0 + 1) * (C / 2)];
            const __nv_bfloat162* p2 = &sXb[(j0 + 2) * (C / 2)];
            const __nv_bfloat162* p3 = &sXb[(j0 + 3) * (C / 2)];
            #pragma unroll
            for (int u4 = 0; u4 < C / 8; u4++) {
                uint4 w0 = *(const uint4*)(p0 + 4 * u4);
                uint4 w1 = *(const uint4*)(p1 + 4 * u4);
                uint4 w2 = *(const uint4*)(p2 + 4 * u4);
                uint4 w3 = *(const uint4*)(p3 + 4 * u4);
                const __nv_bfloat162* h0 = (const __nv_bfloat162*)&w0;
                const __nv_bfloat162* h1 = (const __nv_bfloat162*)&w1;
                const __nv_bfloat162* h2 = (const __nv_bfloat162*)&w2;
                const __nv_bfloat162* h3 = (const __nv_bfloat162*)&w3;
                #pragma unroll
                for (int k = 0; k < 4; k++) {
                    __nv_bfloat162 qv = q2[4 * u4 + k];
                    a0 = __hfma2(qv, h0[k], a0);
                    a1 = __hfma2(qv, h1[k], a1);
                    a2 = __hfma2(qv, h2[k], a2);
                    a3 = __hfma2(qv, h3[k], a3);
                }
            }
            float dd[4];
            dd[0] = __fmaf_rn(-2.f, __low2float(a0) + __high2float(a0), sN[j0 + 0]);
            dd[1] = __fmaf_rn(-2.f, __low2float(a1) + __high2float(a1), sN[j0 + 1]);
            dd[2] = __fmaf_rn(-2.f, __low2float(a2) + __high2float(a2), sN[j0 + 2]);
            dd[3] = __fmaf_rn(-2.f, __low2float(a3) + __high2float(a3), sN[j0 + 3]);
            #pragma unroll
            for (int u = 0; u < 4; u++) {
                int gj = t0 + j0 + u;
                if (dd[u] < worst && gj != qi) {
                    bd[wpos] = dd[u]; bi[wpos] = gj;
                    worst = bd[0]; wpos = 0;
                    #pragma unroll
                    for (int i = 1; i < Kk; i++)
                        if (bd[i] > worst) { worst = bd[i]; wpos = i; }
                }
            }
        }
    }

    int* oci = out_ci + ((size_t)qi * Ss + stripe) * Kk;
    #pragma unroll
    for (int i = 0; i < Kk; i++) oci[i] = bi[i];
}

// ---------------- KNN stage 2: warp-per-query exact re-rank ------------------
// Lane u computes bit-exact round-5 distances (sequential c-ascending
// __fmaf_rn chain per candidate) for candidates m = 4*lane..4*lane+3.
// Selection: rank-based, fully parallel. Set selected = 32 lexicographically
// smallest (d, m) pairs == the set produced by the previous strict-<
// ascending-m replace-worst scan (ties keep earlier m). Output order
// irrelevant downstream (max/min/sum over k are symmetric).
template <int C>
__global__ __launch_bounds__(128)
void exact_select_kernel(const float* __restrict__ X, const float* __restrict__ nrm,
                         const int* __restrict__ ci, int* __restrict__ out_idx) {
    __shared__ float              sQ [4][C];
    __shared__ unsigned long long sKey[4][Mm];
    __shared__ int                sJJ [4][Mm];

    const int w    = threadIdx.x >> 5;
    const int lane = threadIdx.x & 31;
    const int qi   = blockIdx.x * 4 + w;

    for (int c = lane; c < C; c += 32) sQ[w][c] = X[(size_t)qi * C + c];
    __syncwarp();

    const int* mci = ci + (size_t)qi * Mm;
    int4 j4 = *(const int4*)(mci + 4 * lane);
    int js[4] = { j4.x, j4.y, j4.z, j4.w };

    float acc[4] = { 0.f, 0.f, 0.f, 0.f };
    const float* q = sQ[w];
    #pragma unroll 2
    for (int c = 0; c < C; c += 4) {
        float4 qv = *(const float4*)(q + c);   // broadcast LDS
        #pragma unroll
        for (int u = 0; u < 4; u++) {
            float4 v = __ldg((const float4*)(X + (size_t)js[u] * C + c));
            acc[u] = __fmaf_rn(qv.x, v.x, acc[u]);
            acc[u] = __fmaf_rn(qv.y, v.y, acc[u]);
            acc[u] = __fmaf_rn(qv.z, v.z, acc[u]);
            acc[u] = __fmaf_rn(qv.w, v.w, acc[u]);
        }
    }

    const float sqi = nrm[qi];
    unsigned long long myk[4];
    #pragma unroll
    for (int u = 0; u < 4; u++) {
        float d = __fsub_rn(__fadd_rn(sqi, nrm[js[u]]), __fmul_rn(2.0f, acc[u]));
        unsigned ud = __float_as_uint(d);
        ud ^= ((unsigned)((int)ud >> 31)) | 0x80000000u;   // order-preserving map
        myk[u] = ((unsigned long long)ud << 32) | (unsigned)(4 * lane + u);
        sKey[w][4 * lane + u] = myk[u];
        sJJ [w][4 * lane + u] = js[u];
    }
    __syncwarp();

    // parallel rank: count keys strictly smaller (keys all distinct -> unique ranks)
    int rank[4] = { 0, 0, 0, 0 };
    for (int m = 0; m < Mm; m++) {
        unsigned long long km = sKey[w][m];    // broadcast LDS
        #pragma unroll
        for (int u = 0; u < 4; u++) rank[u] += (km < myk[u]);
    }
    #pragma unroll
    for (int u = 0; u < 4; u++)
        if (rank[u] < Kk) out_idx[qi * Kk + rank[u]] = sJJ[w][4 * lane + u];
}

// ---------------- prefix term: A[i][ch] = seq-chain_{c} x_i[c]*Wt[c][ch] ----
template <int C>
__global__ __launch_bounds__(128)
void aterm_kernel(const float* __restrict__ X, const float* __restrict__ Wt,
                  float* __restrict__ A) {
    extern __shared__ float smf[];
    float* sW  = smf;            // C*128
    float* sXi = smf + C * 128;  // C
    const int tid = threadIdx.x;
    for (int l = tid; l < C * 128; l += 128) sW[l] = Wt[l];
    const int NPB = 16;
    for (int v = 0; v < NPB; v++) {
        int n = blockIdx.x * NPB + v;
        __syncthreads();
        if (tid < C) sXi[tid] = X[(size_t)n * C + tid];
        __syncthreads();
        float acc = 0.f;
        #pragma unroll 4
        for (int c = 0; c < C; c++) acc = __fmaf_rn(sXi[c], sW[c * 128 + tid], acc);
        A[(size_t)n * 128 + tid] = acc;
    }
}

// ---------------- fused per-edge conv (round-5 version) ---------------------
template <int C>
__global__ __launch_bounds__(256)
void edge_conv_kernel(const float* __restrict__ X, const float* __restrict__ A,
                      const float* __restrict__ Wb, const float* __restrict__ bias,
                      const int* __restrict__ idx,
                      float* __restrict__ MX, float* __restrict__ MN,
                      double* __restrict__ sum, double* __restrict__ ssq) {
    constexpr int NPB = 8;
    extern __shared__ char smraw[];
    float*  sW   = (float*)smraw;            // C*128
    float*  sD   = sW + C * 128;             // 32*C
    float*  sXi  = sD + 32 * C;              // C
    float*  sB   = sXi + C;                  // 128
    int*    sIdx = (int*)(sB + 128);         // NPB*32
    char*   redraw = (char*)(sIdx + NPB * 32);
    float*  redf = (float*)redraw;
    double* redd = (double*)redraw;          // 16KB region

    const int tid = threadIdx.x;
    const int kt  = tid >> 5;
    const int ct  = tid & 31;
    const int n0  = blockIdx.x * NPB;

    for (int l = tid; l < C * 128; l += 256) sW[l] = Wb[l];
    if (tid < 128) sB[tid] = bias[tid];
    for (int l = tid; l < NPB * 32; l += 256) sIdx[l] = idx[n0 * 32 + l];

    double s_sum[4] = {0, 0, 0, 0};
    double s_ssq[4] = {0, 0, 0, 0};

    for (int v = 0; v < NPB; v++) {
        const int n = n0 + v;
        __syncthreads();
        if (tid < C) sXi[tid] = X[(size_t)n * C + tid];
        __syncthreads();
        for (int l = tid; l < 32 * C; l += 256) {
            int k = l / C, c = l % C;
            int j = sIdx[v * 32 + k];
            sD[l] = __fsub_rn(X[(size_t)j * C + c], sXi[c]);
        }
        __syncthreads();

        float4 a4 = *(const float4*)&A[(size_t)n * 128 + 4 * ct];
        float acc[4][4];
        #pragma unroll
        for (int u = 0; u < 4; u++) {
            acc[u][0] = a4.x; acc[u][1] = a4.y; acc[u][2] = a4.z; acc[u][3] = a4.w;
        }

        #pragma unroll 2
        for (int c = 0; c < C; c += 4) {
            float4 w0 = *(const float4*)&sW[(c + 0) * 128 + 4 * ct];
            float4 w1 = *(const float4*)&sW[(c + 1) * 128 + 4 * ct];
            float4 w2 = *(const float4*)&sW[(c + 2) * 128 + 4 * ct];
            float4 w3 = *(const float4*)&sW[(c + 3) * 128 + 4 * ct];
            #pragma unroll
            for (int u = 0; u < 4; u++) {
                float4 dv = *(const float4*)&sD[(kt + 8 * u) * C + c];
                acc[u][0] = __fmaf_rn(dv.x, w0.x, acc[u][0]);
                acc[u][1] = __fmaf_rn(dv.x, w0.y, acc[u][1]);
                acc[u][2] = __fmaf_rn(dv.x, w0.z, acc[u][2]);
                acc[u][3] = __fmaf_rn(dv.x, w0.w, acc[u][3]);
                acc[u][0] = __fmaf_rn(dv.y, w1.x, acc[u][0]);
                acc[u][1] = __fmaf_rn(dv.y, w1.y, acc[u][1]);
                acc[u][2] = __fmaf_rn(dv.y, w1.z, acc[u][2]);
                acc[u][3] = __fmaf_rn(dv.y, w1.w, acc[u][3]);
                acc[u][0] = __fmaf_rn(dv.z, w2.x, acc[u][0]);
                acc[u][1] = __fmaf_rn(dv.z, w2.y, acc[u][1]);
                acc[u][2] = __fmaf_rn(dv.z, w2.z, acc[u][2]);
                acc[u][3] = __fmaf_rn(dv.z, w2.w, acc[u][3]);
                acc[u][0] = __fmaf_rn(dv.w, w3.x, acc[u][0]);
                acc[u][1] = __fmaf_rn(dv.w, w3.y, acc[u][1]);
                acc[u][2] = __fmaf_rn(dv.w, w3.z, acc[u][2]);
                acc[u][3] = __fmaf_rn(dv.w, w3.w, acc[u][3]);
            }
        }

        #pragma unroll
        for (int j = 0; j < 4; j++) {
            int ch = 4 * ct + j;
            float b = sB[ch];
            float mx = -CUDART_INF_F, mn = CUDART_INF_F;
            #pragma unroll
            for (int u = 0; u < 4; u++) {
                float h = fmaxf(__fadd_rn(acc[u][j], b), 0.f);
                mx = fmaxf(mx, h); mn = fminf(mn, h);
                double hd = (double)h;
                s_sum[j] += hd;
                s_ssq[j] = fma(hd, hd, s_ssq[j]);
            }
            redf[kt * 128 + ch]        = mx;
            redf[1024 + kt * 128 + ch] = mn;
        }
        __syncthreads();
        if (tid < 128) {
            float mx = redf[tid], mn = redf[1024 + tid];
            #pragma unroll
            for (int r = 1; r < 8; r++) {
                mx = fmaxf(mx, redf[r * 128 + tid]);
                mn = fminf(mn, redf[1024 + r * 128 + tid]);
            }
            MX[(size_t)n * 128 + tid] = mx;
            MN[(size_t)n * 128 + tid] = mn;
        }
    }

    __syncthreads();
    #pragma unroll
    for (int j = 0; j < 4; j++) {
        redd[kt * 128 + 4 * ct + j]        = s_sum[j];
        redd[1024 + kt * 128 + 4 * ct + j] = s_ssq[j];
    }
    __syncthreads();
    if (tid < 128) {
        double s = 0.0, s2 = 0.0;
        #pragma unroll
        for (int r = 0; r < 8; r++) {
            s  += redd[r * 128 + tid];
            s2 += redd[1024 + r * 128 + tid];
        }
        atomicAdd(&sum[tid], s);
        atomicAdd(&ssq[tid], s2);
    }
}

// ---------------- BN stats finalize -----------------------------------------
__global__ void bn_finalize_kernel(const double* __restrict__ sum, const double* __restrict__ ssq,
                                   float* __restrict__ mu_out, float* __restrict__ r_out) {
    int ch = threadIdx.x;
    const double inv = 1.0 / ((double)Nn * (double)Kk);
    double mu  = sum[ch] * inv;
    double var = ssq[ch] * inv - mu * mu;
    float vf = (float)var;
    float arg = __fadd_rn(vf, 1e-5f);
    r_out[ch]  = (float)(1.0 / sqrt((double)arg));
    mu_out[ch] = (float)mu;
}

// ---------------- apply BN in ref op order: ((h-mu)*r)*g + beta -------------
__global__ void apply_bn_kernel(const float* __restrict__ mx, const float* __restrict__ mn,
                                const float* __restrict__ mu, const float* __restrict__ r,
                                const float* __restrict__ g, const float* __restrict__ beta,
                                float* __restrict__ out) {
    int i  = blockIdx.x * blockDim.x + threadIdx.x;
    int ch = i & (Hh - 1);
    float gc = g[ch];
    float v  = (gc >= 0.f) ? mx[i] : mn[i];
    out[i] = __fadd_rn(__fmul_rn(__fmul_rn(__fsub_rn(v, mu[ch]), r[ch]), gc), beta[ch]);
}

// ---------------- layer-2 BN + relu + MLP head (sequential chains) ----------
__global__ __launch_bounds__(128)
void final_fused_kernel(const float* __restrict__ mx, const float* __restrict__ mn,
                        const float* __restrict__ mu, const float* __restrict__ r,
                        const float* __restrict__ g, const float* __restrict__ beta,
                        const float* __restrict__ lw1, const float* __restrict__ lb1,
                        const float* __restrict__ lw2, const float* __restrict__ lb2,
                        float* __restrict__ out) {
    __shared__ float sW1[Hh * OUTD];
    __shared__ float sY[2][Hh];
    __shared__ float sT[2][OUTD];
    __shared__ float sB1[OUTD], sB2[OUTD];
    const int t = threadIdx.x;

    for (int l = t; l < Hh * OUTD; l += 128) sW1[l] = lw1[l];
    if (t < OUTD) { sB1[t] = lb1[t]; sB2[t] = lb2[t]; }
    const float muc = mu[t], rc = r[t], gc = g[t], bc = beta[t];
    __syncthreads();

    const int n0 = blockIdx.x * 32;
    for (int p = 0; p < 32; p += 2) {
        const int nA = n0 + p;
        #pragma unroll
        for (int v = 0; v < 2; v++) {
            size_t off = (size_t)(nA + v) * Hh + t;
            float val = (gc >= 0.f) ? mx[off] : mn[off];
            float h2 = __fadd_rn(__fmul_rn(__fmul_rn(__fsub_rn(val, muc), rc), gc), bc);
            sY[v][t] = fmaxf(h2, 0.f);
        }
        __syncthreads();
        {
            int v = t >> 6, o = t & 63;
            float acc = 0.f;
            #pragma unroll 8
            for (int c = 0; c < Hh; c++) acc = __fmaf_rn(sY[v][c], sW1[c * OUTD + o], acc);
            sT[v][o] = fmaxf(__fadd_rn(acc, sB1[o]), 0.f);
        }
        __syncthreads();
        {
            int v = t >> 6, o2 = t & 63;
            float acc = 0.f;
            #pragma unroll 8
            for (int c = 0; c < OUTD; c++)
                acc = __fmaf_rn(sT[v][c], __ldg(&lw2[c * OUTD + o2]), acc);
            out[(size_t)(nA + v) * OUTD + o2] = __fadd_rn(acc, sB2[o2]);
        }
        __syncthreads();
    }
}

// ---------------- launch ------------------------------------------------------
extern "C" void kernel_launch(void* const* d_in, const int* in_sizes, int n_in,
                              void* d_out, int out_size) {
    const float* x     = (const float*)d_in[0];
    const float* W1    = (const float*)d_in[1];
    const float* b1    = (const float*)d_in[2];
    const float* g1    = (const float*)d_in[3];
    const float* beta1 = (const float*)d_in[4];
    const float* W2    = (const float*)d_in[5];
    const float* b2    = (const float*)d_in[6];
    const float* g2    = (const float*)d_in[7];
    const float* beta2 = (const float*)d_in[8];
    const float* lw1   = (const float*)d_in[9];
    const float* lb1   = (const float*)d_in[10];
    const float* lw2   = (const float*)d_in[11];
    const float* lb2   = (const float*)d_in[12];
    float* out = (float*)d_out;

    float *A, *MX, *MN, *H1, *NRM, *MU1, *R1, *MU2, *R2;
    int *IDX, *CI;
    __nv_bfloat162* XB;
    double *SUM1, *SS1, *SUM2, *SS2;
    cudaGetSymbolAddress((void**)&A,    g_A);
    cudaGetSymbolAddress((void**)&MX,   g_MX);
    cudaGetSymbolAddress((void**)&MN,   g_MN);
    cudaGetSymbolAddress((void**)&H1,   g_H1);
    cudaGetSymbolAddress((void**)&IDX,  g_IDX);
    cudaGetSymbolAddress((void**)&NRM,  g_NRM);
    cudaGetSymbolAddress((void**)&CI,   g_CI);
    cudaGetSymbolAddress((void**)&XB,   g_Xb);
    cudaGetSymbolAddress((void**)&SUM1, g_sum1);
    cudaGetSymbolAddress((void**)&SS1,  g_ss1);
    cudaGetSymbolAddress((void**)&SUM2, g_sum2);
    cudaGetSymbolAddress((void**)&SS2,  g_ss2);
    cudaGetSymbolAddress((void**)&MU1,  g_mu1);
    cudaGetSymbolAddress((void**)&R1,   g_r1);
    cudaGetSymbolAddress((void**)&MU2,  g_mu2);
    cudaGetSymbolAddress((void**)&R2,   g_r2);

    int sm_at1 = (Cc * 128 + Cc) * 4;
    int sm_at2 = (Hh * 128 + Hh) * 4;
    int sm_ec1 = (Cc * 128 + 32 * Cc + Cc + 128) * 4 + 8 * 32 * 4 + 2 * 8 * 128 * 8;
    int sm_ec2 = (Hh * 128 + 32 * Hh + Hh + 128) * 4 + 8 * 32 * 4 + 2 * 8 * 128 * 8;
    cudaFuncSetAttribute(aterm_kernel<Cc>,     cudaFuncAttributeMaxDynamicSharedMemorySize, sm_at1);
    cudaFuncSetAttribute(aterm_kernel<Hh>,     cudaFuncAttributeMaxDynamicSharedMemorySize, sm_at2);
    cudaFuncSetAttribute(edge_conv_kernel<Cc>, cudaFuncAttributeMaxDynamicSharedMemorySize, sm_ec1);
    cudaFuncSetAttribute(edge_conv_kernel<Hh>, cudaFuncAttributeMaxDynamicSharedMemorySize, sm_ec2);

    zero_stats_kernel<<<1, 128>>>();

    dim3 kgrid(Nn / 128, Ss);

    // ---- layer 1 ----
    prep_kernel<Cc><<<Nn / 256, 256>>>(x, NRM, XB);
    filter_knn_kernel<Cc, 128><<<kgrid, 128>>>(XB, NRM, CI);
    exact_select_kernel<Cc><<<Nn / 4, 128>>>(x, NRM, CI, IDX);
    aterm_kernel<Cc><<<Nn / 16, 128, sm_at1>>>(x, W1, A);
    edge_conv_kernel<Cc><<<Nn / 8, 256, sm_ec1>>>(x, A, W1 + Cc * Hh, b1, IDX, MX, MN, SUM1, SS1);
    bn_finalize_kernel<<<1, 128>>>(SUM1, SS1, MU1, R1);
    apply_bn_kernel<<<Nn * Hh / 256, 256>>>(MX, MN, MU1, R1, g1, beta1, H1);

    // ---- layer 2 (dynamic graph on h1) ----
    prep_kernel<Hh><<<Nn / 256, 256>>>(H1, NRM, XB);
    filter_knn_kernel<Hh, 128><<<kgrid, 128>>>(XB, NRM, CI);
    exact_select_kernel<Hh><<<Nn / 4, 128>>>(H1, NRM, CI, IDX);
    aterm_kernel<Hh><<<Nn / 16, 128, sm_at2>>>(H1, W2, A);
    edge_conv_kernel<Hh><<<Nn / 8, 256, sm_ec2>>>(H1, A, W2 + Hh * Hh, b2, IDX, MX, MN, SUM2, SS2);
    bn_finalize_kernel<<<1, 128>>>(SUM2, SS2, MU2, R2);

    final_fused_kernel<<<Nn / 32, 128>>>(MX, MN, MU2, R2, g2, beta2, lw1, lb1, lw2, lb2, out);
}

// round 16
// speedup vs baseline: 1.6148x; 1.6148x over previous
#include <cuda_runtime.h>
#include <cuda_bf16.h>
#include <math_constants.h>
#include <cstdint>
#include <cmath>

#define Nn   16384
#define Cc   64
#define Kk   32
#define Hh   128
#define OUTD 64
#define Ss   4          // candidate stripes per query
#define Mm   (Ss * Kk)  // candidates per query after filter (128)

// ---------------- scratch (static device globals) ---------------------------
__device__ float  g_A [Nn * Hh];
__device__ float  g_MX[Nn * Hh];
__device__ float  g_MN[Nn * Hh];
__device__ float  g_H1[Nn * Hh];
__device__ int    g_IDX[Nn * Kk];
__device__ float  g_NRM[Nn];
__device__ int    g_CI[Nn * Mm];               // filtered candidate indices
__device__ __nv_bfloat162 g_Xb[Nn * (Hh / 2)]; // bf16-packed features (filter only)
__device__ double g_sum1[Hh], g_ss1[Hh], g_sum2[Hh], g_ss2[Hh];
__device__ float  g_mu1[Hh], g_r1[Hh], g_mu2[Hh], g_r2[Hh];

__global__ void zero_stats_kernel() {
    int t = threadIdx.x;
    g_sum1[t] = 0.0; g_ss1[t] = 0.0;
    g_sum2[t] = 0.0; g_ss2[t] = 0.0;
}

// ---------------- prep: exact sequential norms + bf16 conversion ------------
template <int C>
__global__ void prep_kernel(const float* __restrict__ X, float* __restrict__ nrm,
                            __nv_bfloat162* __restrict__ Xb) {
    int n = blockIdx.x * blockDim.x + threadIdx.x;
    if (n >= Nn) return;
    const float4* r = (const float4*)(X + (size_t)n * C);
    __nv_bfloat162* ob = Xb + (size_t)n * (C / 2);
    float s = 0.f;
    #pragma unroll
    for (int u = 0; u < C / 4; u++) {
        float4 v = r[u];
        s = __fadd_rn(s, __fmul_rn(v.x, v.x));
        s = __fadd_rn(s, __fmul_rn(v.y, v.y));
        s = __fadd_rn(s, __fmul_rn(v.z, v.z));
        s = __fadd_rn(s, __fmul_rn(v.w, v.w));
        ob[2 * u]     = __floats2bfloat162_rn(v.x, v.y);
        ob[2 * u + 1] = __floats2bfloat162_rn(v.z, v.w);
    }
    nrm[n] = s;
}

// ---------------- KNN stage 1: approximate per-stripe top-K (bf16x2) --------
// d_approx = |x_j|^2 - 2 * dot_bf16(x_i, x_j)  (ranking only — exact pass
// downstream re-ranks with bit-exact fp32 sequential chains).
template <int C, int TC>
__global__ __launch_bounds__(128, 1)
void filter_knn_kernel(const __nv_bfloat162* __restrict__ Xb, const float* __restrict__ nrm,
                       int* __restrict__ out_ci) {
    __shared__ __nv_bfloat162 sXb[TC * (C / 2)];
    __shared__ float sN[TC];

    const int qi     = blockIdx.x * 128 + threadIdx.x;
    const int stripe = blockIdx.y;
    const int cand0  = stripe * (Nn / Ss);
    const int cand1  = cand0 + (Nn / Ss);

    uint4 qraw[C / 8];
    {
        const uint4* xq = (const uint4*)(Xb + (size_t)qi * (C / 2));
        #pragma unroll
        for (int u = 0; u < C / 8; u++) qraw[u] = xq[u];
    }
    const __nv_bfloat162* q2 = (const __nv_bfloat162*)qraw;

    float bd[Kk]; int bi[Kk];
    #pragma unroll
    for (int i = 0; i < Kk; i++) { bd[i] = CUDART_INF_F; bi[i] = 0; }
    float worst = CUDART_INF_F;
    int   wpos  = 0;

    const __nv_bfloat162 z2 = __floats2bfloat162_rn(0.f, 0.f);

    for (int t0 = cand0; t0 < cand1; t0 += TC) {
        __syncthreads();
        const uint4* src = (const uint4*)(Xb + (size_t)t0 * (C / 2));
        for (int l = threadIdx.x; l < TC * C / 8; l += 128) ((uint4*)sXb)[l] = src[l];
        for (int l = threadIdx.x; l < TC; l += 128) sN[l] = nrm[t0 + l];
        __syncthreads();

        for (int j0 = 0; j0 < TC; j0 += 4) {
            __nv_bfloat162 a0 = z2, a1 = z2, a2 = z2, a3 = z2;
            const __nv_bfloat162* p0 = &sXb[(j0 + 0) * (C / 2)];
            const __nv_bfloat162* p1 = &sXb[(j0 + 1) * (C / 2)];
            const __nv_bfloat162* p2 = &sXb[(j0 + 2) * (C / 2)];
            const __nv_bfloat162* p3 = &sXb[(j0 + 3) * (C / 2)];
            #pragma unroll
            for (int u4 = 0; u4 < C / 8; u4++) {
                uint4 w0 = *(const uint4*)(p0 + 4 * u4);
                uint4 w1 = *(const uint4*)(p1 + 4 * u4);
                uint4 w2 = *(const uint4*)(p2 + 4 * u4);
                uint4 w3 = *(const uint4*)(p3 + 4 * u4);
                const __nv_bfloat162* h0 = (const __nv_bfloat162*)&w0;
                const __nv_bfloat162* h1 = (const __nv_bfloat162*)&w1;
                const __nv_bfloat162* h2 = (const __nv_bfloat162*)&w2;
                const __nv_bfloat162* h3 = (const __nv_bfloat162*)&w3;
                #pragma unroll
                for (int k = 0; k < 4; k++) {
                    __nv_bfloat162 qv = q2[4 * u4 + k];
                    a0 = __hfma2(qv, h0[k], a0);
                    a1 = __hfma2(qv, h1[k], a1);
                    a2 = __hfma2(qv, h2[k], a2);
                    a3 = __hfma2(qv, h3[k], a3);
                }
            }
            float dd[4];
            dd[0] = __fmaf_rn(-2.f, __low2float(a0) + __high2float(a0), sN[j0 + 0]);
            dd[1] = __fmaf_rn(-2.f, __low2float(a1) + __high2float(a1), sN[j0 + 1]);
            dd[2] = __fmaf_rn(-2.f, __low2float(a2) + __high2float(a2), sN[j0 + 2]);
            dd[3] = __fmaf_rn(-2.f, __low2float(a3) + __high2float(a3), sN[j0 + 3]);
            #pragma unroll
            for (int u = 0; u < 4; u++) {
                int gj = t0 + j0 + u;
                if (dd[u] < worst && gj != qi) {
                    bd[wpos] = dd[u]; bi[wpos] = gj;
                    worst = bd[0]; wpos = 0;
                    #pragma unroll
                    for (int i = 1; i < Kk; i++)
                        if (bd[i] > worst) { worst = bd[i]; wpos = i; }
                }
            }
        }
    }

    int* oci = out_ci + ((size_t)qi * Ss + stripe) * Kk;
    #pragma unroll
    for (int i = 0; i < Kk; i++) oci[i] = bi[i];
}

// ---------------- KNN stage 2: warp-per-query exact re-rank ------------------
// Lane u computes bit-exact round-5 distances (sequential c-ascending
// __fmaf_rn chain per candidate) for candidates m = 4*lane..4*lane+3.
// Selection: rank-based, fully parallel. Selected set = 32 lexicographically
// smallest (d, m) pairs (= true exact top-32 of the candidate pool).
// Output order irrelevant downstream (max/min/sum over k are symmetric).
template <int C>
__global__ __launch_bounds__(128)
void exact_select_kernel(const float* __restrict__ X, const float* __restrict__ nrm,
                         const int* __restrict__ ci, int* __restrict__ out_idx) {
    __shared__ float              sQ [4][C];
    __shared__ unsigned long long sKey[4][Mm];
    __shared__ int                sJJ [4][Mm];

    const int w    = threadIdx.x >> 5;
    const int lane = threadIdx.x & 31;
    const int qi   = blockIdx.x * 4 + w;

    for (int c = lane; c < C; c += 32) sQ[w][c] = X[(size_t)qi * C + c];
    __syncwarp();

    const int* mci = ci + (size_t)qi * Mm;
    int4 j4 = *(const int4*)(mci + 4 * lane);
    int js[4] = { j4.x, j4.y, j4.z, j4.w };

    float acc[4] = { 0.f, 0.f, 0.f, 0.f };
    const float* q = sQ[w];
    #pragma unroll 2
    for (int c = 0; c < C; c += 4) {
        float4 qv = *(const float4*)(q + c);   // broadcast LDS
        #pragma unroll
        for (int u = 0; u < 4; u++) {
            float4 v = __ldg((const float4*)(X + (size_t)js[u] * C + c));
            acc[u] = __fmaf_rn(qv.x, v.x, acc[u]);
            acc[u] = __fmaf_rn(qv.y, v.y, acc[u]);
            acc[u] = __fmaf_rn(qv.z, v.z, acc[u]);
            acc[u] = __fmaf_rn(qv.w, v.w, acc[u]);
        }
    }

    const float sqi = nrm[qi];
    unsigned long long myk[4];
    #pragma unroll
    for (int u = 0; u < 4; u++) {
        float d = __fsub_rn(__fadd_rn(sqi, nrm[js[u]]), __fmul_rn(2.0f, acc[u]));
        unsigned ud = __float_as_uint(d);
        ud ^= ((unsigned)((int)ud >> 31)) | 0x80000000u;   // order-preserving map
        myk[u] = ((unsigned long long)ud << 32) | (unsigned)(4 * lane + u);
        sKey[w][4 * lane + u] = myk[u];
        sJJ [w][4 * lane + u] = js[u];
    }
    __syncwarp();

    // parallel rank: count keys strictly smaller (keys all distinct -> unique ranks)
    int rank[4] = { 0, 0, 0, 0 };
    for (int m = 0; m < Mm; m++) {
        unsigned long long km = sKey[w][m];    // broadcast LDS
        #pragma unroll
        for (int u = 0; u < 4; u++) rank[u] += (km < myk[u]);
    }
    #pragma unroll
    for (int u = 0; u < 4; u++)
        if (rank[u] < Kk) out_idx[qi * Kk + rank[u]] = sJJ[w][4 * lane + u];
}

// ---------------- prefix term: A[i][ch] = seq-chain_{c} x_i[c]*Wt[c][ch] ----
template <int C>
__global__ __launch_bounds__(128)
void aterm_kernel(const float* __restrict__ X, const float* __restrict__ Wt,
                  float* __restrict__ A) {
    extern __shared__ float smf[];
    float* sW  = smf;            // C*128
    float* sXi = smf + C * 128;  // C
    const int tid = threadIdx.x;
    for (int l = tid; l < C * 128; l += 128) sW[l] = Wt[l];
    const int NPB = 16;
    for (int v = 0; v < NPB; v++) {
        int n = blockIdx.x * NPB + v;
        __syncthreads();
        if (tid < C) sXi[tid] = X[(size_t)n * C + tid];
        __syncthreads();
        float acc = 0.f;
        #pragma unroll 4
        for (int c = 0; c < C; c++) acc = __fmaf_rn(sXi[c], sW[c * 128 + tid], acc);
        A[(size_t)n * 128 + tid] = acc;
    }
}

// ---------------- fused per-edge conv (round-5 version) ---------------------
template <int C>
__global__ __launch_bounds__(256)
void edge_conv_kernel(const float* __restrict__ X, const float* __restrict__ A,
                      const float* __restrict__ Wb, const float* __restrict__ bias,
                      const int* __restrict__ idx,
                      float* __restrict__ MX, float* __restrict__ MN,
                      double* __restrict__ sum, double* __restrict__ ssq) {
    constexpr int NPB = 8;
    extern __shared__ char smraw[];
    float*  sW   = (float*)smraw;            // C*128
    float*  sD   = sW + C * 128;             // 32*C
    float*  sXi  = sD + 32 * C;              // C
    float*  sB   = sXi + C;                  // 128
    int*    sIdx = (int*)(sB + 128);         // NPB*32
    char*   redraw = (char*)(sIdx + NPB * 32);
    float*  redf = (float*)redraw;
    double* redd = (double*)redraw;          // 16KB region

    const int tid = threadIdx.x;
    const int kt  = tid >> 5;
    const int ct  = tid & 31;
    const int n0  = blockIdx.x * NPB;

    for (int l = tid; l < C * 128; l += 256) sW[l] = Wb[l];
    if (tid < 128) sB[tid] = bias[tid];
    for (int l = tid; l < NPB * 32; l += 256) sIdx[l] = idx[n0 * 32 + l];

    double s_sum[4] = {0, 0, 0, 0};
    double s_ssq[4] = {0, 0, 0, 0};

    for (int v = 0; v < NPB; v++) {
        const int n = n0 + v;
        __syncthreads();
        if (tid < C) sXi[tid] = X[(size_t)n * C + tid];
        __syncthreads();
        for (int l = tid; l < 32 * C; l += 256) {
            int k = l / C, c = l % C;
            int j = sIdx[v * 32 + k];
            sD[l] = __fsub_rn(X[(size_t)j * C + c], sXi[c]);
        }
        __syncthreads();

        float4 a4 = *(const float4*)&A[(size_t)n * 128 + 4 * ct];
        float acc[4][4];
        #pragma unroll
        for (int u = 0; u < 4; u++) {
            acc[u][0] = a4.x; acc[u][1] = a4.y; acc[u][2] = a4.z; acc[u][3] = a4.w;
        }

        #pragma unroll 2
        for (int c = 0; c < C; c += 4) {
            float4 w0 = *(const float4*)&sW[(c + 0) * 128 + 4 * ct];
            float4 w1 = *(const float4*)&sW[(c + 1) * 128 + 4 * ct];
            float4 w2 = *(const float4*)&sW[(c + 2) * 128 + 4 * ct];
            float4 w3 = *(const float4*)&sW[(c + 3) * 128 + 4 * ct];
            #pragma unroll
            for (int u = 0; u < 4; u++) {
                float4 dv = *(const float4*)&sD[(kt + 8 * u) * C + c];
                acc[u][0] = __fmaf_rn(dv.x, w0.x, acc[u][0]);
                acc[u][1] = __fmaf_rn(dv.x, w0.y, acc[u][1]);
                acc[u][2] = __fmaf_rn(dv.x, w0.z, acc[u][2]);
                acc[u][3] = __fmaf_rn(dv.x, w0.w, acc[u][3]);
                acc[u][0] = __fmaf_rn(dv.y, w1.x, acc[u][0]);
                acc[u][1] = __fmaf_rn(dv.y, w1.y, acc[u][1]);
                acc[u][2] = __fmaf_rn(dv.y, w1.z, acc[u][2]);
                acc[u][3] = __fmaf_rn(dv.y, w1.w, acc[u][3]);
                acc[u][0] = __fmaf_rn(dv.z, w2.x, acc[u][0]);
                acc[u][1] = __fmaf_rn(dv.z, w2.y, acc[u][1]);
                acc[u][2] = __fmaf_rn(dv.z, w2.z, acc[u][2]);
                acc[u][3] = __fmaf_rn(dv.z, w2.w, acc[u][3]);
                acc[u][0] = __fmaf_rn(dv.w, w3.x, acc[u][0]);
                acc[u][1] = __fmaf_rn(dv.w, w3.y, acc[u][1]);
                acc[u][2] = __fmaf_rn(dv.w, w3.z, acc[u][2]);
                acc[u][3] = __fmaf_rn(dv.w, w3.w, acc[u][3]);
            }
        }

        #pragma unroll
        for (int j = 0; j < 4; j++) {
            int ch = 4 * ct + j;
            float b = sB[ch];
            float mx = -CUDART_INF_F, mn = CUDART_INF_F;
            #pragma unroll
            for (int u = 0; u < 4; u++) {
                float h = fmaxf(__fadd_rn(acc[u][j], b), 0.f);
                mx = fmaxf(mx, h); mn = fminf(mn, h);
                double hd = (double)h;
                s_sum[j] += hd;
                s_ssq[j] = fma(hd, hd, s_ssq[j]);
            }
            redf[kt * 128 + ch]        = mx;
            redf[1024 + kt * 128 + ch] = mn;
        }
        __syncthreads();
        if (tid < 128) {
            float mx = redf[tid], mn = redf[1024 + tid];
            #pragma unroll
            for (int r = 1; r < 8; r++) {
                mx = fmaxf(mx, redf[r * 128 + tid]);
                mn = fminf(mn, redf[1024 + r * 128 + tid]);
            }
            MX[(size_t)n * 128 + tid] = mx;
            MN[(size_t)n * 128 + tid] = mn;
        }
    }

    __syncthreads();
    #pragma unroll
    for (int j = 0; j < 4; j++) {
        redd[kt * 128 + 4 * ct + j]        = s_sum[j];
        redd[1024 + kt * 128 + 4 * ct + j] = s_ssq[j];
    }
    __syncthreads();
    if (tid < 128) {
        double s = 0.0, s2 = 0.0;
        #pragma unroll
        for (int r = 0; r < 8; r++) {
            s  += redd[r * 128 + tid];
            s2 += redd[1024 + r * 128 + tid];
        }
        atomicAdd(&sum[tid], s);
        atomicAdd(&ssq[tid], s2);
    }
}

// ---------------- BN stats finalize -----------------------------------------
__global__ void bn_finalize_kernel(const double* __restrict__ sum, const double* __restrict__ ssq,
                                   float* __restrict__ mu_out, float* __restrict__ r_out) {
    int ch = threadIdx.x;
    const double inv = 1.0 / ((double)Nn * (double)Kk);
    double mu  = sum[ch] * inv;
    double var = ssq[ch] * inv - mu * mu;
    float vf = (float)var;
    float arg = __fadd_rn(vf, 1e-5f);
    r_out[ch]  = (float)(1.0 / sqrt((double)arg));
    mu_out[ch] = (float)mu;
}

// ---------------- apply BN in ref op order: ((h-mu)*r)*g + beta -------------
__global__ void apply_bn_kernel(const float* __restrict__ mx, const float* __restrict__ mn,
                                const float* __restrict__ mu, const float* __restrict__ r,
                                const float* __restrict__ g, const float* __restrict__ beta,
                                float* __restrict__ out) {
    int i  = blockIdx.x * blockDim.x + threadIdx.x;
    int ch = i & (Hh - 1);
    float gc = g[ch];
    float v  = (gc >= 0.f) ? mx[i] : mn[i];
    out[i] = __fadd_rn(__fmul_rn(__fmul_rn(__fsub_rn(v, mu[ch]), r[ch]), gc), beta[ch]);
}

// ---------------- layer-2 BN + relu + MLP head (sequential chains) ----------
__global__ __launch_bounds__(128)
void final_fused_kernel(const float* __restrict__ mx, const float* __restrict__ mn,
                        const float* __restrict__ mu, const float* __restrict__ r,
                        const float* __restrict__ g, const float* __restrict__ beta,
                        const float* __restrict__ lw1, const float* __restrict__ lb1,
                        const float* __restrict__ lw2, const float* __restrict__ lb2,
                        float* __restrict__ out) {
    __shared__ float sW1[Hh * OUTD];
    __shared__ float sY[2][Hh];
    __shared__ float sT[2][OUTD];
    __shared__ float sB1[OUTD], sB2[OUTD];
    const int t = threadIdx.x;

    for (int l = t; l < Hh * OUTD; l += 128) sW1[l] = lw1[l];
    if (t < OUTD) { sB1[t] = lb1[t]; sB2[t] = lb2[t]; }
    const float muc = mu[t], rc = r[t], gc = g[t], bc = beta[t];
    __syncthreads();

    const int n0 = blockIdx.x * 32;
    for (int p = 0; p < 32; p += 2) {
        const int nA = n0 + p;
        #pragma unroll
        for (int v = 0; v < 2; v++) {
            size_t off = (size_t)(nA + v) * Hh + t;
            float val = (gc >= 0.f) ? mx[off] : mn[off];
            float h2 = __fadd_rn(__fmul_rn(__fmul_rn(__fsub_rn(val, muc), rc), gc), bc);
            sY[v][t] = fmaxf(h2, 0.f);
        }
        __syncthreads();
        {
            int v = t >> 6, o = t & 63;
            float acc = 0.f;
            #pragma unroll 8
            for (int c = 0; c < Hh; c++) acc = __fmaf_rn(sY[v][c], sW1[c * OUTD + o], acc);
            sT[v][o] = fmaxf(__fadd_rn(acc, sB1[o]), 0.f);
        }
        __syncthreads();
        {
            int v = t >> 6, o2 = t & 63;
            float acc = 0.f;
            #pragma unroll 8
            for (int c = 0; c < OUTD; c++)
                acc = __fmaf_rn(sT[v][c], __ldg(&lw2[c * OUTD + o2]), acc);
            out[(size_t)(nA + v) * OUTD + o2] = __fadd_rn(acc, sB2[o2]);
        }
        __syncthreads();
    }
}

// ---------------- launch ------------------------------------------------------
extern "C" void kernel_launch(void* const* d_in, const int* in_sizes, int n_in,
                              void* d_out, int out_size) {
    const float* x     = (const float*)d_in[0];
    const float* W1    = (const float*)d_in[1];
    const float* b1    = (const float*)d_in[2];
    const float* g1    = (const float*)d_in[3];
    const float* beta1 = (const float*)d_in[4];
    const float* W2    = (const float*)d_in[5];
    const float* b2    = (const float*)d_in[6];
    const float* g2    = (const float*)d_in[7];
    const float* beta2 = (const float*)d_in[8];
    const float* lw1   = (const float*)d_in[9];
    const float* lb1   = (const float*)d_in[10];
    const float* lw2   = (const float*)d_in[11];
    const float* lb2   = (const float*)d_in[12];
    float* out = (float*)d_out;

    float *A, *MX, *MN, *H1, *NRM, *MU1, *R1, *MU2, *R2;
    int *IDX, *CI;
    __nv_bfloat162* XB;
    double *SUM1, *SS1, *SUM2, *SS2;
    cudaGetSymbolAddress((void**)&A,    g_A);
    cudaGetSymbolAddress((void**)&MX,   g_MX);
    cudaGetSymbolAddress((void**)&MN,   g_MN);
    cudaGetSymbolAddress((void**)&H1,   g_H1);
    cudaGetSymbolAddress((void**)&IDX,  g_IDX);
    cudaGetSymbolAddress((void**)&NRM,  g_NRM);
    cudaGetSymbolAddress((void**)&CI,   g_CI);
    cudaGetSymbolAddress((void**)&XB,   g_Xb);
    cudaGetSymbolAddress((void**)&SUM1, g_sum1);
    cudaGetSymbolAddress((void**)&SS1,  g_ss1);
    cudaGetSymbolAddress((void**)&SUM2, g_sum2);
    cudaGetSymbolAddress((void**)&SS2,  g_ss2);
    cudaGetSymbolAddress((void**)&MU1,  g_mu1);
    cudaGetSymbolAddress((void**)&R1,   g_r1);
    cudaGetSymbolAddress((void**)&MU2,  g_mu2);
    cudaGetSymbolAddress((void**)&R2,   g_r2);

    int sm_at1 = (Cc * 128 + Cc) * 4;
    int sm_at2 = (Hh * 128 + Hh) * 4;
    int sm_ec1 = (Cc * 128 + 32 * Cc + Cc + 128) * 4 + 8 * 32 * 4 + 2 * 8 * 128 * 8;
    int sm_ec2 = (Hh * 128 + 32 * Hh + Hh + 128) * 4 + 8 * 32 * 4 + 2 * 8 * 128 * 8;
    cudaFuncSetAttribute(aterm_kernel<Cc>,     cudaFuncAttributeMaxDynamicSharedMemorySize, sm_at1);
    cudaFuncSetAttribute(aterm_kernel<Hh>,     cudaFuncAttributeMaxDynamicSharedMemorySize, sm_at2);
    cudaFuncSetAttribute(edge_conv_kernel<Cc>, cudaFuncAttributeMaxDynamicSharedMemorySize, sm_ec1);
    cudaFuncSetAttribute(edge_conv_kernel<Hh>, cudaFuncAttributeMaxDynamicSharedMemorySize, sm_ec2);

    zero_stats_kernel<<<1, 128>>>();

    dim3 kgrid(Nn / 128, Ss);

    // ---- layer 1 ----
    prep_kernel<Cc><<<Nn / 256, 256>>>(x, NRM, XB);
    filter_knn_kernel<Cc, 128><<<kgrid, 128>>>(XB, NRM, CI);
    exact_select_kernel<Cc><<<Nn / 4, 128>>>(x, NRM, CI, IDX);
    aterm_kernel<Cc><<<Nn / 16, 128, sm_at1>>>(x, W1, A);
    edge_conv_kernel<Cc><<<Nn / 8, 256, sm_ec1>>>(x, A, W1 + Cc * Hh, b1, IDX, MX, MN, SUM1, SS1);
    bn_finalize_kernel<<<1, 128>>>(SUM1, SS1, MU1, R1);
    apply_bn_kernel<<<Nn * Hh / 256, 256>>>(MX, MN, MU1, R1, g1, beta1, H1);

    // ---- layer 2 (dynamic graph on h1) ----
    prep_kernel<Hh><<<Nn / 256, 256>>>(H1, NRM, XB);
    filter_knn_kernel<Hh, 128><<<kgrid, 128>>>(XB, NRM, CI);
    exact_select_kernel<Hh><<<Nn / 4, 128>>>(H1, NRM, CI, IDX);
    aterm_kernel<Hh><<<Nn / 16, 128, sm_at2>>>(H1, W2, A);
    edge_conv_kernel<Hh><<<Nn / 8, 256, sm_ec2>>>(H1, A, W2 + Hh * Hh, b2, IDX, MX, MN, SUM2, SS2);
    bn_finalize_kernel<<<1, 128>>>(SUM2, SS2, MU2, R2);

    final_fused_kernel<<<Nn / 32, 128>>>(MX, MN, MU2, R2, g2, beta2, lw1, lb1, lw2, lb2, out);
}

// round 17
// speedup vs baseline: 2.0269x; 1.2552x over previous
#include <cuda_runtime.h>
#include <math_constants.h>
#include <cstdint>
#include <cmath>

#define Nn   16384
#define Cc   64
#define Kk   32
#define Hh   128
#define OUTD 64
#define Ss   4          // candidate stripes per query
#define Mm   (Ss * Kk)  // candidates per query after filter (128)

// ---------------- scratch (static device globals) ---------------------------
__device__ float  g_A [Nn * Hh];
__device__ float  g_MX[Nn * Hh];
__device__ float  g_MN[Nn * Hh];
__device__ float  g_H1[Nn * Hh];
__device__ int    g_IDX[Nn * Kk];
__device__ float  g_NRM[Nn];
__device__ float  g_SCL[Nn];                   // per-row int8 scale
__device__ int    g_CI[Nn * Mm];               // filtered candidate indices
__device__ int    g_Xq[Nn * (Hh / 4)];         // int8-packed features (filter only)
__device__ double g_sum1[Hh], g_ss1[Hh], g_sum2[Hh], g_ss2[Hh];
__device__ float  g_mu1[Hh], g_r1[Hh], g_mu2[Hh], g_r2[Hh];

__global__ void zero_stats_kernel() {
    int t = threadIdx.x;
    g_sum1[t] = 0.0; g_ss1[t] = 0.0;
    g_sum2[t] = 0.0; g_ss2[t] = 0.0;
}

// ---------------- prep: exact norms + per-row int8 quantization -------------
template <int C>
__global__ void prep_kernel(const float* __restrict__ X, float* __restrict__ nrm,
                            float* __restrict__ scl, int* __restrict__ Xq) {
    int n = blockIdx.x * blockDim.x + threadIdx.x;
    if (n >= Nn) return;
    const float4* r = (const float4*)(X + (size_t)n * C);
    float s = 0.f, mx = 0.f;
    #pragma unroll
    for (int u = 0; u < C / 4; u++) {
        float4 v = r[u];
        s = __fadd_rn(s, __fmul_rn(v.x, v.x));
        s = __fadd_rn(s, __fmul_rn(v.y, v.y));
        s = __fadd_rn(s, __fmul_rn(v.z, v.z));
        s = __fadd_rn(s, __fmul_rn(v.w, v.w));
        mx = fmaxf(mx, fmaxf(fmaxf(fabsf(v.x), fabsf(v.y)),
                             fmaxf(fabsf(v.z), fabsf(v.w))));
    }
    nrm[n] = s;
    float inv = (mx > 0.f) ? (127.f / mx) : 0.f;
    scl[n] = (mx > 0.f) ? (mx / 127.f) : 0.f;
    int* oq = Xq + (size_t)n * (C / 4);
    #pragma unroll
    for (int u = 0; u < C / 4; u++) {
        float4 v = r[u];                       // L1 hit
        int q0 = __float2int_rn(v.x * inv) & 255;
        int q1 = __float2int_rn(v.y * inv) & 255;
        int q2 = __float2int_rn(v.z * inv) & 255;
        int q3 = __float2int_rn(v.w * inv) & 255;
        oq[u] = q0 | (q1 << 8) | (q2 << 16) | (q3 << 24);
    }
}

// ---------------- KNN stage 1: approximate per-stripe top-K (int8 dp4a) -----
// ranking key d = |x_j|^2 - 2*si*sj*dot_int8(x_i,x_j)  (ranking only — exact
// fp32 pass downstream re-ranks, so the final output depends only on the
// candidate pool covering the true top-32).
template <int C, int TC>
__global__ __launch_bounds__(128, 1)
void filter_knn_kernel(const int* __restrict__ Xq, const float* __restrict__ nrm,
                       const float* __restrict__ scl, int* __restrict__ out_ci) {
    __shared__ int   sXq[TC * (C / 4)];
    __shared__ float sN[TC];
    __shared__ float sS[TC];

    const int qi     = blockIdx.x * 128 + threadIdx.x;
    const int stripe = blockIdx.y;
    const int cand0  = stripe * (Nn / Ss);
    const int cand1  = cand0 + (Nn / Ss);

    int q[C / 4];
    {
        const int4* xq = (const int4*)(Xq + (size_t)qi * (C / 4));
        #pragma unroll
        for (int u = 0; u < C / 16; u++) {
            int4 v = xq[u];
            q[4*u] = v.x; q[4*u+1] = v.y; q[4*u+2] = v.z; q[4*u+3] = v.w;
        }
    }
    const float t2s = 2.f * scl[qi];

    float bd[Kk]; int bi[Kk];
    #pragma unroll
    for (int i = 0; i < Kk; i++) { bd[i] = CUDART_INF_F; bi[i] = 0; }
    float worst = CUDART_INF_F;
    int   wpos  = 0;

    for (int t0 = cand0; t0 < cand1; t0 += TC) {
        __syncthreads();
        const int4* src = (const int4*)(Xq + (size_t)t0 * (C / 4));
        for (int l = threadIdx.x; l < TC * C / 16; l += 128) ((int4*)sXq)[l] = src[l];
        for (int l = threadIdx.x; l < TC; l += 128) {
            sN[l] = nrm[t0 + l];
            sS[l] = scl[t0 + l];
        }
        __syncthreads();

        for (int j0 = 0; j0 < TC; j0 += 4) {
            int a0 = 0, a1 = 0, a2 = 0, a3 = 0;
            const int* p0 = &sXq[(j0 + 0) * (C / 4)];
            const int* p1 = &sXq[(j0 + 1) * (C / 4)];
            const int* p2 = &sXq[(j0 + 2) * (C / 4)];
            const int* p3 = &sXq[(j0 + 3) * (C / 4)];
            #pragma unroll
            for (int u = 0; u < C / 16; u++) {
                int4 v0 = *(const int4*)(p0 + 4 * u);
                int4 v1 = *(const int4*)(p1 + 4 * u);
                int4 v2 = *(const int4*)(p2 + 4 * u);
                int4 v3 = *(const int4*)(p3 + 4 * u);
                a0 = __dp4a(q[4*u+0], v0.x, a0); a0 = __dp4a(q[4*u+1], v0.y, a0);
                a0 = __dp4a(q[4*u+2], v0.z, a0); a0 = __dp4a(q[4*u+3], v0.w, a0);
                a1 = __dp4a(q[4*u+0], v1.x, a1); a1 = __dp4a(q[4*u+1], v1.y, a1);
                a1 = __dp4a(q[4*u+2], v1.z, a1); a1 = __dp4a(q[4*u+3], v1.w, a1);
                a2 = __dp4a(q[4*u+0], v2.x, a2); a2 = __dp4a(q[4*u+1], v2.y, a2);
                a2 = __dp4a(q[4*u+2], v2.z, a2); a2 = __dp4a(q[4*u+3], v2.w, a2);
                a3 = __dp4a(q[4*u+0], v3.x, a3); a3 = __dp4a(q[4*u+1], v3.y, a3);
                a3 = __dp4a(q[4*u+2], v3.z, a3); a3 = __dp4a(q[4*u+3], v3.w, a3);
            }
            float dd[4];
            dd[0] = __fmaf_rn(-(t2s * sS[j0 + 0]), (float)a0, sN[j0 + 0]);
            dd[1] = __fmaf_rn(-(t2s * sS[j0 + 1]), (float)a1, sN[j0 + 1]);
            dd[2] = __fmaf_rn(-(t2s * sS[j0 + 2]), (float)a2, sN[j0 + 2]);
            dd[3] = __fmaf_rn(-(t2s * sS[j0 + 3]), (float)a3, sN[j0 + 3]);
            #pragma unroll
            for (int u = 0; u < 4; u++) {
                int gj = t0 + j0 + u;
                if (dd[u] < worst && gj != qi) {
                    bd[wpos] = dd[u]; bi[wpos] = gj;
                    worst = bd[0]; wpos = 0;
                    #pragma unroll
                    for (int i = 1; i < Kk; i++)
                        if (bd[i] > worst) { worst = bd[i]; wpos = i; }
                }
            }
        }
    }

    int* oci = out_ci + ((size_t)qi * Ss + stripe) * Kk;
    #pragma unroll
    for (int i = 0; i < Kk; i++) oci[i] = bi[i];
}

// ---------------- KNN stage 2: warp-per-query exact re-rank ------------------
// Lane u computes bit-exact round-5 distances (sequential c-ascending
// __fmaf_rn chain per candidate) for candidates m = 4*lane..4*lane+3.
// Selection: rank-based, fully parallel (32 smallest (d,m) lexicographic).
template <int C>
__global__ __launch_bounds__(128)
void exact_select_kernel(const float* __restrict__ X, const float* __restrict__ nrm,
                         const int* __restrict__ ci, int* __restrict__ out_idx) {
    __shared__ float              sQ [4][C];
    __shared__ unsigned long long sKey[4][Mm];
    __shared__ int                sJJ [4][Mm];

    const int w    = threadIdx.x >> 5;
    const int lane = threadIdx.x & 31;
    const int qi   = blockIdx.x * 4 + w;

    for (int c = lane; c < C; c += 32) sQ[w][c] = X[(size_t)qi * C + c];
    __syncwarp();

    const int* mci = ci + (size_t)qi * Mm;
    int4 j4 = *(const int4*)(mci + 4 * lane);
    int js[4] = { j4.x, j4.y, j4.z, j4.w };

    float acc[4] = { 0.f, 0.f, 0.f, 0.f };
    const float* q = sQ[w];
    #pragma unroll 2
    for (int c = 0; c < C; c += 4) {
        float4 qv = *(const float4*)(q + c);   // broadcast LDS
        #pragma unroll
        for (int u = 0; u < 4; u++) {
            float4 v = __ldg((const float4*)(X + (size_t)js[u] * C + c));
            acc[u] = __fmaf_rn(qv.x, v.x, acc[u]);
            acc[u] = __fmaf_rn(qv.y, v.y, acc[u]);
            acc[u] = __fmaf_rn(qv.z, v.z, acc[u]);
            acc[u] = __fmaf_rn(qv.w, v.w, acc[u]);
        }
    }

    const float sqi = nrm[qi];
    unsigned long long myk[4];
    #pragma unroll
    for (int u = 0; u < 4; u++) {
        float d = __fsub_rn(__fadd_rn(sqi, nrm[js[u]]), __fmul_rn(2.0f, acc[u]));
        unsigned ud = __float_as_uint(d);
        ud ^= ((unsigned)((int)ud >> 31)) | 0x80000000u;   // order-preserving map
        myk[u] = ((unsigned long long)ud << 32) | (unsigned)(4 * lane + u);
        sKey[w][4 * lane + u] = myk[u];
        sJJ [w][4 * lane + u] = js[u];
    }
    __syncwarp();

    int rank[4] = { 0, 0, 0, 0 };
    for (int m = 0; m < Mm; m++) {
        unsigned long long km = sKey[w][m];    // broadcast LDS
        #pragma unroll
        for (int u = 0; u < 4; u++) rank[u] += (km < myk[u]);
    }
    #pragma unroll
    for (int u = 0; u < 4; u++)
        if (rank[u] < Kk) out_idx[qi * Kk + rank[u]] = sJJ[w][4 * lane + u];
}

// ---------------- prefix term: A[i][ch] = seq-chain_{c} x_i[c]*Wt[c][ch] ----
template <int C>
__global__ __launch_bounds__(128)
void aterm_kernel(const float* __restrict__ X, const float* __restrict__ Wt,
                  float* __restrict__ A) {
    extern __shared__ float smf[];
    float* sW  = smf;            // C*128
    float* sXi = smf + C * 128;  // C
    const int tid = threadIdx.x;
    for (int l = tid; l < C * 128; l += 128) sW[l] = Wt[l];
    const int NPB = 16;
    for (int v = 0; v < NPB; v++) {
        int n = blockIdx.x * NPB + v;
        __syncthreads();
        if (tid < C) sXi[tid] = X[(size_t)n * C + tid];
        __syncthreads();
        float acc = 0.f;
        #pragma unroll 4
        for (int c = 0; c < C; c++) acc = __fmaf_rn(sXi[c], sW[c * 128 + tid], acc);
        A[(size_t)n * 128 + tid] = acc;
    }
}

// ---------------- fused per-edge conv (round-5 version) ---------------------
template <int C>
__global__ __launch_bounds__(256)
void edge_conv_kernel(const float* __restrict__ X, const float* __restrict__ A,
                      const float* __restrict__ Wb, const float* __restrict__ bias,
                      const int* __restrict__ idx,
                      float* __restrict__ MX, float* __restrict__ MN,
                      double* __restrict__ sum, double* __restrict__ ssq) {
    constexpr int NPB = 8;
    extern __shared__ char smraw[];
    float*  sW   = (float*)smraw;            // C*128
    float*  sD   = sW + C * 128;             // 32*C
    float*  sXi  = sD + 32 * C;              // C
    float*  sB   = sXi + C;                  // 128
    int*    sIdx = (int*)(sB + 128);         // NPB*32
    char*   redraw = (char*)(sIdx + NPB * 32);
    float*  redf = (float*)redraw;
    double* redd = (double*)redraw;          // 16KB region

    const int tid = threadIdx.x;
    const int kt  = tid >> 5;
    const int ct  = tid & 31;
    const int n0  = blockIdx.x * NPB;

    for (int l = tid; l < C * 128; l += 256) sW[l] = Wb[l];
    if (tid < 128) sB[tid] = bias[tid];
    for (int l = tid; l < NPB * 32; l += 256) sIdx[l] = idx[n0 * 32 + l];

    double s_sum[4] = {0, 0, 0, 0};
    double s_ssq[4] = {0, 0, 0, 0};

    for (int v = 0; v < NPB; v++) {
        const int n = n0 + v;
        __syncthreads();
        if (tid < C) sXi[tid] = X[(size_t)n * C + tid];
        __syncthreads();
        for (int l = tid; l < 32 * C; l += 256) {
            int k = l / C, c = l % C;
            int j = sIdx[v * 32 + k];
            sD[l] = __fsub_rn(X[(size_t)j * C + c], sXi[c]);
        }
        __syncthreads();

        float4 a4 = *(const float4*)&A[(size_t)n * 128 + 4 * ct];
        float acc[4][4];
        #pragma unroll
        for (int u = 0; u < 4; u++) {
            acc[u][0] = a4.x; acc[u][1] = a4.y; acc[u][2] = a4.z; acc[u][3] = a4.w;
        }

        #pragma unroll 2
        for (int c = 0; c < C; c += 4) {
            float4 w0 = *(const float4*)&sW[(c + 0) * 128 + 4 * ct];
            float4 w1 = *(const float4*)&sW[(c + 1) * 128 + 4 * ct];
            float4 w2 = *(const float4*)&sW[(c + 2) * 128 + 4 * ct];
            float4 w3 = *(const float4*)&sW[(c + 3) * 128 + 4 * ct];
            #pragma unroll
            for (int u = 0; u < 4; u++) {
                float4 dv = *(const float4*)&sD[(kt + 8 * u) * C + c];
                acc[u][0] = __fmaf_rn(dv.x, w0.x, acc[u][0]);
                acc[u][1] = __fmaf_rn(dv.x, w0.y, acc[u][1]);
                acc[u][2] = __fmaf_rn(dv.x, w0.z, acc[u][2]);
                acc[u][3] = __fmaf_rn(dv.x, w0.w, acc[u][3]);
                acc[u][0] = __fmaf_rn(dv.y, w1.x, acc[u][0]);
                acc[u][1] = __fmaf_rn(dv.y, w1.y, acc[u][1]);
                acc[u][2] = __fmaf_rn(dv.y, w1.z, acc[u][2]);
                acc[u][3] = __fmaf_rn(dv.y, w1.w, acc[u][3]);
                acc[u][0] = __fmaf_rn(dv.z, w2.x, acc[u][0]);
                acc[u][1] = __fmaf_rn(dv.z, w2.y, acc[u][1]);
                acc[u][2] = __fmaf_rn(dv.z, w2.z, acc[u][2]);
                acc[u][3] = __fmaf_rn(dv.z, w2.w, acc[u][3]);
                acc[u][0] = __fmaf_rn(dv.w, w3.x, acc[u][0]);
                acc[u][1] = __fmaf_rn(dv.w, w3.y, acc[u][1]);
                acc[u][2] = __fmaf_rn(dv.w, w3.z, acc[u][2]);
                acc[u][3] = __fmaf_rn(dv.w, w3.w, acc[u][3]);
            }
        }

        #pragma unroll
        for (int j = 0; j < 4; j++) {
            int ch = 4 * ct + j;
            float b = sB[ch];
            float mx = -CUDART_INF_F, mn = CUDART_INF_F;
            #pragma unroll
            for (int u = 0; u < 4; u++) {
                float h = fmaxf(__fadd_rn(acc[u][j], b), 0.f);
                mx = fmaxf(mx, h); mn = fminf(mn, h);
                double hd = (double)h;
                s_sum[j] += hd;
                s_ssq[j] = fma(hd, hd, s_ssq[j]);
            }
            redf[kt * 128 + ch]        = mx;
            redf[1024 + kt * 128 + ch] = mn;
        }
        __syncthreads();
        if (tid < 128) {
            float mx = redf[tid], mn = redf[1024 + tid];
            #pragma unroll
            for (int r = 1; r < 8; r++) {
                mx = fmaxf(mx, redf[r * 128 + tid]);
                mn = fminf(mn, redf[1024 + r * 128 + tid]);
            }
            MX[(size_t)n * 128 + tid] = mx;
            MN[(size_t)n * 128 + tid] = mn;
        }
    }

    __syncthreads();
    #pragma unroll
    for (int j = 0; j < 4; j++) {
        redd[kt * 128 + 4 * ct + j]        = s_sum[j];
        redd[1024 + kt * 128 + 4 * ct + j] = s_ssq[j];
    }
    __syncthreads();
    if (tid < 128) {
        double s = 0.0, s2 = 0.0;
        #pragma unroll
        for (int r = 0; r < 8; r++) {
            s  += redd[r * 128 + tid];
            s2 += redd[1024 + r * 128 + tid];
        }
        atomicAdd(&sum[tid], s);
        atomicAdd(&ssq[tid], s2);
    }
}

// ---------------- BN stats finalize -----------------------------------------
__global__ void bn_finalize_kernel(const double* __restrict__ sum, const double* __restrict__ ssq,
                                   float* __restrict__ mu_out, float* __restrict__ r_out) {
    int ch = threadIdx.x;
    const double inv = 1.0 / ((double)Nn * (double)Kk);
    double mu  = sum[ch] * inv;
    double var = ssq[ch] * inv - mu * mu;
    float vf = (float)var;
    float arg = __fadd_rn(vf, 1e-5f);
    r_out[ch]  = (float)(1.0 / sqrt((double)arg));
    mu_out[ch] = (float)mu;
}

// ---------------- apply BN in ref op order: ((h-mu)*r)*g + beta -------------
__global__ void apply_bn_kernel(const float* __restrict__ mx, const float* __restrict__ mn,
                                const float* __restrict__ mu, const float* __restrict__ r,
                                const float* __restrict__ g, const float* __restrict__ beta,
                                float* __restrict__ out) {
    int i  = blockIdx.x * blockDim.x + threadIdx.x;
    int ch = i & (Hh - 1);
    float gc = g[ch];
    float v  = (gc >= 0.f) ? mx[i] : mn[i];
    out[i] = __fadd_rn(__fmul_rn(__fmul_rn(__fsub_rn(v, mu[ch]), r[ch]), gc), beta[ch]);
}

// ---------------- layer-2 BN + relu + MLP head (sequential chains) ----------
__global__ __launch_bounds__(128)
void final_fused_kernel(const float* __restrict__ mx, const float* __restrict__ mn,
                        const float* __restrict__ mu, const float* __restrict__ r,
                        const float* __restrict__ g, const float* __restrict__ beta,
                        const float* __restrict__ lw1, const float* __restrict__ lb1,
                        const float* __restrict__ lw2, const float* __restrict__ lb2,
                        float* __restrict__ out) {
    __shared__ float sW1[Hh * OUTD];
    __shared__ float sY[2][Hh];
    __shared__ float sT[2][OUTD];
    __shared__ float sB1[OUTD], sB2[OUTD];
    const int t = threadIdx.x;

    for (int l = t; l < Hh * OUTD; l += 128) sW1[l] = lw1[l];
    if (t < OUTD) { sB1[t] = lb1[t]; sB2[t] = lb2[t]; }
    const float muc = mu[t], rc = r[t], gc = g[t], bc = beta[t];
    __syncthreads();

    const int n0 = blockIdx.x * 32;
    for (int p = 0; p < 32; p += 2) {
        const int nA = n0 + p;
        #pragma unroll
        for (int v = 0; v < 2; v++) {
            size_t off = (size_t)(nA + v) * Hh + t;
            float val = (gc >= 0.f) ? mx[off] : mn[off];
            float h2 = __fadd_rn(__fmul_rn(__fmul_rn(__fsub_rn(val, muc), rc), gc), bc);
            sY[v][t] = fmaxf(h2, 0.f);
        }
        __syncthreads();
        {
            int v = t >> 6, o = t & 63;
            float acc = 0.f;
            #pragma unroll 8
            for (int c = 0; c < Hh; c++) acc = __fmaf_rn(sY[v][c], sW1[c * OUTD + o], acc);
            sT[v][o] = fmaxf(__fadd_rn(acc, sB1[o]), 0.f);
        }
        __syncthreads();
        {
            int v = t >> 6, o2 = t & 63;
            float acc = 0.f;
            #pragma unroll 8
            for (int c = 0; c < OUTD; c++)
                acc = __fmaf_rn(sT[v][c], __ldg(&lw2[c * OUTD + o2]), acc);
            out[(size_t)(nA + v) * OUTD + o2] = __fadd_rn(acc, sB2[o2]);
        }
        __syncthreads();
    }
}

// ---------------- launch ------------------------------------------------------
extern "C" void kernel_launch(void* const* d_in, const int* in_sizes, int n_in,
                              void* d_out, int out_size) {
    const float* x     = (const float*)d_in[0];
    const float* W1    = (const float*)d_in[1];
    const float* b1    = (const float*)d_in[2];
    const float* g1    = (const float*)d_in[3];
    const float* beta1 = (const float*)d_in[4];
    const float* W2    = (const float*)d_in[5];
    const float* b2    = (const float*)d_in[6];
    const float* g2    = (const float*)d_in[7];
    const float* beta2 = (const float*)d_in[8];
    const float* lw1   = (const float*)d_in[9];
    const float* lb1   = (const float*)d_in[10];
    const float* lw2   = (const float*)d_in[11];
    const float* lb2   = (const float*)d_in[12];
    float* out = (float*)d_out;

    float *A, *MX, *MN, *H1, *NRM, *SCL, *MU1, *R1, *MU2, *R2;
    int *IDX, *CI, *XQ;
    double *SUM1, *SS1, *SUM2, *SS2;
    cudaGetSymbolAddress((void**)&A,    g_A);
    cudaGetSymbolAddress((void**)&MX,   g_MX);
    cudaGetSymbolAddress((void**)&MN,   g_MN);
    cudaGetSymbolAddress((void**)&H1,   g_H1);
    cudaGetSymbolAddress((void**)&IDX,  g_IDX);
    cudaGetSymbolAddress((void**)&NRM,  g_NRM);
    cudaGetSymbolAddress((void**)&SCL,  g_SCL);
    cudaGetSymbolAddress((void**)&CI,   g_CI);
    cudaGetSymbolAddress((void**)&XQ,   g_Xq);
    cudaGetSymbolAddress((void**)&SUM1, g_sum1);
    cudaGetSymbolAddress((void**)&SS1,  g_ss1);
    cudaGetSymbolAddress((void**)&SUM2, g_sum2);
    cudaGetSymbolAddress((void**)&SS2,  g_ss2);
    cudaGetSymbolAddress((void**)&MU1,  g_mu1);
    cudaGetSymbolAddress((void**)&R1,   g_r1);
    cudaGetSymbolAddress((void**)&MU2,  g_mu2);
    cudaGetSymbolAddress((void**)&R2,   g_r2);

    int sm_at1 = (Cc * 128 + Cc) * 4;
    int sm_at2 = (Hh * 128 + Hh) * 4;
    int sm_ec1 = (Cc * 128 + 32 * Cc + Cc + 128) * 4 + 8 * 32 * 4 + 2 * 8 * 128 * 8;
    int sm_ec2 = (Hh * 128 + 32 * Hh + Hh + 128) * 4 + 8 * 32 * 4 + 2 * 8 * 128 * 8;
    cudaFuncSetAttribute(aterm_kernel<Cc>,     cudaFuncAttributeMaxDynamicSharedMemorySize, sm_at1);
    cudaFuncSetAttribute(aterm_kernel<Hh>,     cudaFuncAttributeMaxDynamicSharedMemorySize, sm_at2);
    cudaFuncSetAttribute(edge_conv_kernel<Cc>, cudaFuncAttributeMaxDynamicSharedMemorySize, sm_ec1);
    cudaFuncSetAttribute(edge_conv_kernel<Hh>, cudaFuncAttributeMaxDynamicSharedMemorySize, sm_ec2);

    zero_stats_kernel<<<1, 128>>>();

    dim3 kgrid(Nn / 128, Ss);

    // ---- layer 1 ----
    prep_kernel<Cc><<<Nn / 256, 256>>>(x, NRM, SCL, XQ);
    filter_knn_kernel<Cc, 128><<<kgrid, 128>>>(XQ, NRM, SCL, CI);
    exact_select_kernel<Cc><<<Nn / 4, 128>>>(x, NRM, CI, IDX);
    aterm_kernel<Cc><<<Nn / 16, 128, sm_at1>>>(x, W1, A);
    edge_conv_kernel<Cc><<<Nn / 8, 256, sm_ec1>>>(x, A, W1 + Cc * Hh, b1, IDX, MX, MN, SUM1, SS1);
    bn_finalize_kernel<<<1, 128>>>(SUM1, SS1, MU1, R1);
    apply_bn_kernel<<<Nn * Hh / 256, 256>>>(MX, MN, MU1, R1, g1, beta1, H1);

    // ---- layer 2 (dynamic graph on h1) ----
    prep_kernel<Hh><<<Nn / 256, 256>>>(H1, NRM, SCL, XQ);
    filter_knn_kernel<Hh, 128><<<kgrid, 128>>>(XQ, NRM, SCL, CI);
    exact_select_kernel<Hh><<<Nn / 4, 128>>>(H1, NRM, CI, IDX);
    aterm_kernel<Hh><<<Nn / 16, 128, sm_at2>>>(H1, W2, A);
    edge_conv_kernel<Hh><<<Nn / 8, 256, sm_ec2>>>(H1, A, W2 + Hh * Hh, b2, IDX, MX, MN, SUM2, SS2);
    bn_finalize_kernel<<<1, 128>>>(SUM2, SS2, MU2, R2);

    final_fused_kernel<<<Nn / 32, 128>>>(MX, MN, MU2, R2, g2, beta2, lw1, lb1, lw2, lb2, out);
}